// round 7
// baseline (speedup 1.0000x reference)
#include <cuda_runtime.h>
#include <cuda_fp16.h>
#include <cstdint>
#include <cstddef>

#define NDIM   4096
#define BT     128            // C tile 128x128
#define KT     64             // k elements per pipeline stage
#define STAGES 5
#define SROW   144            // smem bytes per tile row (128B data + 16B pad)
#define TILE_B (128 * SROW)   // 18432 B
#define STAGE_B (2 * TILE_B)  // Ah + Bh = 36864 B
#define DSMEM_BYTES (STAGES * STAGE_B)  // 184320 B -> 1 CTA/SM

// Single-pass fp16 scratch. B transposed to [n][k].
static __device__ __half g_Ah[(size_t)NDIM * NDIM];
static __device__ __half g_Bh[(size_t)NDIM * NDIM];   // [n][k]

// ---------------------------------------------------------------------------
// Fused pre-pass over 32x32 tiles. z=0: A -> fp16 (tiles with ct <= rt|3);
// z=1: B -> Bh[n][k] transpose (k-tiles >= (n-tile & ~3)).
// ---------------------------------------------------------------------------
__global__ void conv_kernel(const float* __restrict__ A, const float* __restrict__ B) {
    __shared__ float tile[32][33];
    const int tid = threadIdx.x;

    if (blockIdx.z == 0) {
        const int rt = blockIdx.y, ct = blockIdx.x;
        if (ct > (rt | 3)) return;
        const int r = rt * 32 + (tid >> 3);
        const int c = ct * 32 + (tid & 7) * 4;
        const float4 v = *reinterpret_cast<const float4*>(A + (size_t)r * NDIM + c);
        *reinterpret_cast<ushort4*>(g_Ah + (size_t)r * NDIM + c) =
            make_ushort4(__half_as_ushort(__float2half(v.x)),
                         __half_as_ushort(__float2half(v.y)),
                         __half_as_ushort(__float2half(v.z)),
                         __half_as_ushort(__float2half(v.w)));
        return;
    }

    const int nt = blockIdx.y, kt = blockIdx.x;
    if (kt < (nt & ~3)) return;
    const int bk = kt * 32, bn = nt * 32;
    const int x = tid & 31, y0 = tid >> 5;
    #pragma unroll
    for (int yy = y0; yy < 32; yy += 8)
        tile[yy][x] = B[(size_t)(bk + yy) * NDIM + bn + x];
    __syncthreads();
    #pragma unroll
    for (int yy = y0; yy < 32; yy += 8)
        g_Bh[(size_t)(bn + yy) * NDIM + bk + x] = __float2half(tile[x][yy]);
}

// ---------------------------------------------------------------------------
__device__ __forceinline__ uint32_t smem_u32(const void* p) {
    uint32_t a;
    asm("{ .reg .u64 t; cvta.to.shared.u64 t, %1; cvt.u32.u64 %0, t; }" : "=r"(a) : "l"(p));
    return a;
}
__device__ __forceinline__ void cpa16(uint32_t dst, const void* src) {
    asm volatile("cp.async.cg.shared.global [%0], [%1], 16;\n" ::"r"(dst), "l"(src));
}

#define LDSM4(r0, r1, r2, r3, addr)                                                    \
    asm volatile("ldmatrix.sync.aligned.m8n8.x4.shared.b16 {%0,%1,%2,%3}, [%4];"       \
                 : "=r"(r0), "=r"(r1), "=r"(r2), "=r"(r3) : "r"(addr))

#define MMA_F16(d, a, b0, b1)                                                          \
    asm volatile(                                                                      \
        "mma.sync.aligned.m16n8k16.row.col.f32.f16.f16.f32 "                           \
        "{%0,%1,%2,%3}, {%4,%5,%6,%7}, {%8,%9}, {%0,%1,%2,%3};\n"                      \
        : "+f"((d)[0]), "+f"((d)[1]), "+f"((d)[2]), "+f"((d)[3])                       \
        : "r"((a)[0]), "r"((a)[1]), "r"((a)[2]), "r"((a)[3]), "r"(b0), "r"(b1))

// Load one k16 slice of fragments (A 2x LDSM.x4, B 4x LDSM.x4).
#define LD_FRAGS(fa, fb, st, kb)                                                       \
    do {                                                                               \
        LDSM4((fa)[0][0], (fa)[0][1], (fa)[0][2], (fa)[0][3], (st) + a_off[0] + (kb)); \
        LDSM4((fa)[1][0], (fa)[1][1], (fa)[1][2], (fa)[1][3], (st) + a_off[1] + (kb)); \
        LDSM4((fb)[0][0], (fb)[0][1], (fb)[0][2], (fb)[0][3], (st) + b_off[0] + (kb)); \
        LDSM4((fb)[1][0], (fb)[1][1], (fb)[1][2], (fb)[1][3], (st) + b_off[1] + (kb)); \
        LDSM4((fb)[2][0], (fb)[2][1], (fb)[2][2], (fb)[2][3], (st) + b_off[2] + (kb)); \
        LDSM4((fb)[3][0], (fb)[3][1], (fb)[3][2], (fb)[3][3], (st) + b_off[3] + (kb)); \
    } while (0)

#define MMA_ALL(fa, fb)                                                                \
    do {                                                                               \
        _Pragma("unroll") for (int mi = 0; mi < 2; mi++)                               \
            _Pragma("unroll") for (int p = 0; p < 4; p++) {                            \
                MMA_F16(acc[mi][2 * p],     (fa)[mi], (fb)[p][0], (fb)[p][1]);         \
                MMA_F16(acc[mi][2 * p + 1], (fa)[mi], (fb)[p][2], (fb)[p][3]);         \
            }                                                                          \
    } while (0)

// ---------------------------------------------------------------------------
// Triangular GEMM, single-pass fp16, 5-stage cp.async pipeline, 1 CTA/SM,
// double-buffered register fragments, per-warp structural-zero kk skipping.
// ---------------------------------------------------------------------------
__global__ __launch_bounds__(256) void trimm_kernel(float* __restrict__ C) {
    extern __shared__ char dsm[];
    const int tid = threadIdx.x;
    const int lane = tid & 31, warp = tid >> 5;

    if (blockIdx.x >= 528) {
        int u = blockIdx.x - 528, r = 0;
        #pragma unroll 1
        while (u >= 31 - r) { u -= 31 - r; r++; }
        const int m0 = r * BT, n0 = (r + 1 + u) * BT;
        const float4 z = make_float4(0.f, 0.f, 0.f, 0.f);
        #pragma unroll 1
        for (int i = tid; i < 128 * 32; i += 256)
            reinterpret_cast<float4*>(C + (size_t)(m0 + (i >> 5)) * NDIM + n0)[i & 31] = z;
        return;
    }

    // Lower-triangle tile, bm descending (LPT + strip reuse).
    int t = blockIdx.x, bm = 31;
    #pragma unroll 1
    while (t >= bm + 1) { t -= bm + 1; bm--; }
    const int bn = t;
    const int m0 = bm * BT, n0 = bn * BT;
    const int T = ((bm - bn) + 1) * 2;            // k64 chunks; min 2

    const uint32_t sb = smem_u32(dsm);

    // cp.async mapping: 4 cps per tile per thread.
    const int cr0 = tid >> 3, cc = tid & 7;
    const __half* gAh = g_Ah + (size_t)(m0 + cr0) * NDIM + cc * 8;
    const __half* gBh = g_Bh + (size_t)(n0 + cr0) * NDIM + cc * 8;
    const uint32_t cdst = sb + cr0 * SROW + cc * 16;

    // Warp tile 32m x 64n.
    const int wm = (warp >> 1) * 32, wn = (warp & 1) * 64;
    const int mlim = m0 + wm + 31;                // A slice zero if k0 > mlim
    const int nlim = n0 + wn;                     // B slice zero if k0+16 <= nlim
    uint32_t a_off[2], b_off[4];
    #pragma unroll
    for (int mi = 0; mi < 2; mi++)
        a_off[mi] = (uint32_t)((wm + mi * 16 + (lane & 15)) * SROW + (lane >> 4) * 16);
    #pragma unroll
    for (int p = 0; p < 4; p++) {
        const int quad = lane >> 3;
        b_off[p] = (uint32_t)(TILE_B + (wn + p * 16 + (quad >> 1) * 8 + (lane & 7)) * SROW +
                              (quad & 1) * 16);
    }

    float acc[2][8][4];
    #pragma unroll
    for (int mi = 0; mi < 2; mi++)
        #pragma unroll
        for (int ni = 0; ni < 8; ni++)
            #pragma unroll
            for (int r = 0; r < 4; r++) acc[mi][ni][r] = 0.f;

    // Prologue: commit chunks 0..3 (empty groups beyond T keep positions aligned).
    #pragma unroll
    for (int s = 0; s < STAGES - 1; s++) {
        if (s < T) {
            const int k0 = n0 + s * KT;
            const uint32_t d = cdst + s * STAGE_B;
            #pragma unroll
            for (int i = 0; i < 4; i++) {
                cpa16(d + i * 32 * SROW, gAh + (size_t)i * 32 * NDIM + k0);
                cpa16(d + TILE_B + i * 32 * SROW, gBh + (size_t)i * 32 * NDIM + k0);
            }
        }
        asm volatile("cp.async.commit_group;\n");
    }

    uint32_t fa0[2][4], fb0[4][4], fa1[2][4], fb1[4][4];

    #pragma unroll 1
    for (int it = 0; it < T; it++) {
        const int k0 = n0 + it * KT;
        // All but newest 3 groups done => chunk `it` resident.
        asm volatile("cp.async.wait_group %0;\n" ::"n"(STAGES - 2));
        __syncthreads();   // chunk it visible; all warps past compute(it-1)

        // Prefetch chunk it+4 into slot (it-1)%5 (safe per the barrier above).
        const int ch = it + STAGES - 1;
        if (ch < T) {
            const int kp = n0 + ch * KT;
            const uint32_t d = cdst + (ch % STAGES) * STAGE_B;
            #pragma unroll
            for (int i = 0; i < 4; i++) {
                cpa16(d + i * 32 * SROW, gAh + (size_t)i * 32 * NDIM + kp);
                cpa16(d + TILE_B + i * 32 * SROW, gBh + (size_t)i * 32 * NDIM + kp);
            }
        }
        asm volatile("cp.async.commit_group;\n");

        const uint32_t st = sb + (it % STAGES) * STAGE_B;

        // Structural-zero skips (warp-uniform): slice kk all-zero if its k-range
        // is entirely right of A's diagonal or left of B's diagonal.
        bool sk[4];
        #pragma unroll
        for (int kk = 0; kk < 4; kk++)
            sk[kk] = (k0 + 16 * kk > mlim) || (k0 + 16 * kk + 16 <= nlim);

        // Double-buffered fragment pipeline over 4 k16 slices.
        if (!sk[0]) LD_FRAGS(fa0, fb0, st, 0);
        if (!sk[1]) LD_FRAGS(fa1, fb1, st, 32);
        if (!sk[0]) MMA_ALL(fa0, fb0);
        if (!sk[2]) LD_FRAGS(fa0, fb0, st, 64);
        if (!sk[1]) MMA_ALL(fa1, fb1);
        if (!sk[3]) LD_FRAGS(fa1, fb1, st, 96);
        if (!sk[2]) MMA_ALL(fa0, fb0);
        if (!sk[3]) MMA_ALL(fa1, fb1);
    }

    // Epilogue.
    const int g = lane >> 2, tg = lane & 3;
    #pragma unroll
    for (int mi = 0; mi < 2; mi++)
        #pragma unroll
        for (int ni = 0; ni < 8; ni++) {
            const int r0 = m0 + wm + mi * 16 + g;
            const int c0 = n0 + wn + ni * 8 + tg * 2;
            *reinterpret_cast<float2*>(C + (size_t)r0 * NDIM + c0) =
                make_float2(acc[mi][ni][0], acc[mi][ni][1]);
            *reinterpret_cast<float2*>(C + (size_t)(r0 + 8) * NDIM + c0) =
                make_float2(acc[mi][ni][2], acc[mi][ni][3]);
        }
}

// ---------------------------------------------------------------------------
extern "C" void kernel_launch(void* const* d_in, const int* in_sizes, int n_in,
                              void* d_out, int out_size) {
    (void)in_sizes; (void)n_in; (void)out_size;
    const float* A = (const float*)d_in[0];
    const float* B = (const float*)d_in[1];
    float* C = (float*)d_out;

    static bool attr_done = false;
    if (!attr_done) {
        cudaFuncSetAttribute(trimm_kernel, cudaFuncAttributeMaxDynamicSharedMemorySize,
                             DSMEM_BYTES);
        attr_done = true;
    }

    conv_kernel<<<dim3(128, 128, 2), 256>>>(A, B);
    trimm_kernel<<<1024, 256, DSMEM_BYTES>>>(C);
}

// round 8
// speedup vs baseline: 1.0247x; 1.0247x over previous
#include <cuda_runtime.h>
#include <cuda_fp16.h>
#include <cstdint>
#include <cstddef>

#define NDIM   4096
#define BT     128            // C tile 128x128
#define KT     64             // k elements per pipeline stage
#define STAGES 3
#define SROW   144            // smem bytes per tile row (128B data + 16B pad)
#define TILE_B (128 * SROW)   // 18432 B
#define STAGE_B (2 * TILE_B)  // Ah + Bh = 36864 B
#define DSMEM_BYTES (STAGES * STAGE_B)  // 110592 B -> 2 CTAs/SM

// Single-pass fp16 scratch. B transposed to [n][k].
static __device__ __half g_Ah[(size_t)NDIM * NDIM];
static __device__ __half g_Bh[(size_t)NDIM * NDIM];   // [n][k]

// ---------------------------------------------------------------------------
// Fused pre-pass over 32x32 tiles. z=0: A -> fp16 (tiles with ct <= rt|3);
// z=1: B -> Bh[n][k] transpose (k-tiles >= (n-tile & ~3)).
// ---------------------------------------------------------------------------
__global__ void conv_kernel(const float* __restrict__ A, const float* __restrict__ B) {
    __shared__ float tile[32][33];
    const int tid = threadIdx.x;

    if (blockIdx.z == 0) {
        const int rt = blockIdx.y, ct = blockIdx.x;
        if (ct > (rt | 3)) return;
        const int r = rt * 32 + (tid >> 3);
        const int c = ct * 32 + (tid & 7) * 4;
        const float4 v = *reinterpret_cast<const float4*>(A + (size_t)r * NDIM + c);
        *reinterpret_cast<ushort4*>(g_Ah + (size_t)r * NDIM + c) =
            make_ushort4(__half_as_ushort(__float2half(v.x)),
                         __half_as_ushort(__float2half(v.y)),
                         __half_as_ushort(__float2half(v.z)),
                         __half_as_ushort(__float2half(v.w)));
        return;
    }

    const int nt = blockIdx.y, kt = blockIdx.x;
    if (kt < (nt & ~3)) return;
    const int bk = kt * 32, bn = nt * 32;
    const int x = tid & 31, y0 = tid >> 5;
    #pragma unroll
    for (int yy = y0; yy < 32; yy += 8)
        tile[yy][x] = B[(size_t)(bk + yy) * NDIM + bn + x];
    __syncthreads();
    #pragma unroll
    for (int yy = y0; yy < 32; yy += 8)
        g_Bh[(size_t)(bn + yy) * NDIM + bk + x] = __float2half(tile[x][yy]);
}

// ---------------------------------------------------------------------------
__device__ __forceinline__ uint32_t smem_u32(const void* p) {
    uint32_t a;
    asm("{ .reg .u64 t; cvta.to.shared.u64 t, %1; cvt.u32.u64 %0, t; }" : "=r"(a) : "l"(p));
    return a;
}
__device__ __forceinline__ void cpa16(uint32_t dst, const void* src) {
    asm volatile("cp.async.cg.shared.global [%0], [%1], 16;\n" ::"r"(dst), "l"(src));
}

#define LDSM4(r0, r1, r2, r3, addr)                                                    \
    asm volatile("ldmatrix.sync.aligned.m8n8.x4.shared.b16 {%0,%1,%2,%3}, [%4];"       \
                 : "=r"(r0), "=r"(r1), "=r"(r2), "=r"(r3) : "r"(addr))

#define MMA_F16(d, a, b0, b1)                                                          \
    asm volatile(                                                                      \
        "mma.sync.aligned.m16n8k16.row.col.f32.f16.f16.f32 "                           \
        "{%0,%1,%2,%3}, {%4,%5,%6,%7}, {%8,%9}, {%0,%1,%2,%3};\n"                      \
        : "+f"((d)[0]), "+f"((d)[1]), "+f"((d)[2]), "+f"((d)[3])                       \
        : "r"((a)[0]), "r"((a)[1]), "r"((a)[2]), "r"((a)[3]), "r"(b0), "r"(b1))

// Load the 4 B fragments (64 n) for one k16 slice into buffer fb.
#define LD_B(fb, st, kb)                                                               \
    do {                                                                               \
        LDSM4((fb)[0][0], (fb)[0][1], (fb)[0][2], (fb)[0][3], (st) + b_off[0] + (kb)); \
        LDSM4((fb)[1][0], (fb)[1][1], (fb)[1][2], (fb)[1][3], (st) + b_off[1] + (kb)); \
        LDSM4((fb)[2][0], (fb)[2][1], (fb)[2][2], (fb)[2][3], (st) + b_off[2] + (kb)); \
        LDSM4((fb)[3][0], (fb)[3][1], (fb)[3][2], (fb)[3][3], (st) + b_off[3] + (kb)); \
    } while (0)

// JIT A-half load (16 rows) + its 8 MMAs against buffer fb.
#define A_MMA_HALF(mi, fb, st, kb)                                                     \
    do {                                                                               \
        uint32_t fa[4];                                                                \
        LDSM4(fa[0], fa[1], fa[2], fa[3], (st) + a_off[mi] + (kb));                    \
        _Pragma("unroll") for (int p = 0; p < 4; p++) {                                \
            MMA_F16(acc[mi][2 * p],     fa, (fb)[p][0], (fb)[p][1]);                   \
            MMA_F16(acc[mi][2 * p + 1], fa, (fb)[p][2], (fb)[p][3]);                   \
        }                                                                              \
    } while (0)

// ---------------------------------------------------------------------------
// Triangular GEMM, single-pass fp16, 3-stage cp.async pipeline, 2 CTAs/SM,
// B-fragment double buffering to break LDSM/MMA phase alternation.
// ---------------------------------------------------------------------------
__global__ __launch_bounds__(256, 2) void trimm_kernel(float* __restrict__ C) {
    extern __shared__ char dsm[];
    const int tid = threadIdx.x;
    const int lane = tid & 31, warp = tid >> 5;

    if (blockIdx.x >= 528) {
        int u = blockIdx.x - 528, r = 0;
        #pragma unroll 1
        while (u >= 31 - r) { u -= 31 - r; r++; }
        const int m0 = r * BT, n0 = (r + 1 + u) * BT;
        const float4 z = make_float4(0.f, 0.f, 0.f, 0.f);
        #pragma unroll 1
        for (int i = tid; i < 128 * 32; i += 256)
            reinterpret_cast<float4*>(C + (size_t)(m0 + (i >> 5)) * NDIM + n0)[i & 31] = z;
        return;
    }

    // Lower-triangle tile, bm descending (LPT + strip reuse).
    int t = blockIdx.x, bm = 31;
    #pragma unroll 1
    while (t >= bm + 1) { t -= bm + 1; bm--; }
    const int bn = t;
    const int m0 = bm * BT, n0 = bn * BT;
    const int T = ((bm - bn) + 1) * 2;            // k64 chunks; min 2

    const uint32_t sb = smem_u32(dsm);

    // cp.async mapping: 4 cps per tile per thread.
    const int cr0 = tid >> 3, cc = tid & 7;
    const __half* gAh = g_Ah + (size_t)(m0 + cr0) * NDIM + cc * 8;
    const __half* gBh = g_Bh + (size_t)(n0 + cr0) * NDIM + cc * 8;
    const uint32_t cdst = sb + cr0 * SROW + cc * 16;

    // Warp tile 32m x 64n.
    const int wm = (warp >> 1) * 32, wn = (warp & 1) * 64;
    const int mlim = m0 + wm + 31;                // A slice zero if k0 > mlim
    const int nlim = n0 + wn;                     // B slice zero if k0+16 <= nlim
    uint32_t a_off[2], b_off[4];
    #pragma unroll
    for (int mi = 0; mi < 2; mi++)
        a_off[mi] = (uint32_t)((wm + mi * 16 + (lane & 15)) * SROW + (lane >> 4) * 16);
    #pragma unroll
    for (int p = 0; p < 4; p++) {
        const int quad = lane >> 3;
        b_off[p] = (uint32_t)(TILE_B + (wn + p * 16 + (quad >> 1) * 8 + (lane & 7)) * SROW +
                              (quad & 1) * 16);
    }

    float acc[2][8][4];
    #pragma unroll
    for (int mi = 0; mi < 2; mi++)
        #pragma unroll
        for (int ni = 0; ni < 8; ni++)
            #pragma unroll
            for (int r = 0; r < 4; r++) acc[mi][ni][r] = 0.f;

    // Prologue: commit chunks 0,1 (T >= 2 always).
    #pragma unroll
    for (int s = 0; s < STAGES - 1; s++) {
        const int k0 = n0 + s * KT;
        const uint32_t d = cdst + s * STAGE_B;
        #pragma unroll
        for (int i = 0; i < 4; i++) {
            cpa16(d + i * 32 * SROW, gAh + (size_t)i * 32 * NDIM + k0);
            cpa16(d + TILE_B + i * 32 * SROW, gBh + (size_t)i * 32 * NDIM + k0);
        }
        asm volatile("cp.async.commit_group;\n");
    }

    uint32_t fb0[4][4], fb1[4][4];

    #pragma unroll 1
    for (int it = 0; it < T; it++) {
        const int k0 = n0 + it * KT;
        asm volatile("cp.async.wait_group 1;\n");   // chunk it resident
        __syncthreads();                            // visible; warps past it-1

        // Prefetch chunk it+2 into slot (it-1)%3 (safe per the barrier).
        const int ch = it + 2;
        if (ch < T) {
            const int kp = n0 + ch * KT;
            const uint32_t d = cdst + (ch % STAGES) * STAGE_B;
            #pragma unroll
            for (int i = 0; i < 4; i++) {
                cpa16(d + i * 32 * SROW, gAh + (size_t)i * 32 * NDIM + kp);
                cpa16(d + TILE_B + i * 32 * SROW, gBh + (size_t)i * 32 * NDIM + kp);
            }
        }
        asm volatile("cp.async.commit_group;\n");

        const uint32_t st = sb + (it % STAGES) * STAGE_B;

        // Structural-zero slices (warp-uniform).
        bool sk[4];
        #pragma unroll
        for (int kk = 0; kk < 4; kk++)
            sk[kk] = (k0 + 16 * kk > mlim) || (k0 + 16 * kk + 16 <= nlim);

        // B double-buffered, A loaded just-in-time per 16-row half:
        // B(kk+1) prefetch is issued before kk's MMAs so LDSM and HMMA overlap.
        if (!sk[0]) LD_B(fb0, st, 0);
        if (!sk[1]) LD_B(fb1, st, 32);
        if (!sk[0]) { A_MMA_HALF(0, fb0, st, 0);  A_MMA_HALF(1, fb0, st, 0); }
        if (!sk[2]) LD_B(fb0, st, 64);
        if (!sk[1]) { A_MMA_HALF(0, fb1, st, 32); A_MMA_HALF(1, fb1, st, 32); }
        if (!sk[3]) LD_B(fb1, st, 96);
        if (!sk[2]) { A_MMA_HALF(0, fb0, st, 64); A_MMA_HALF(1, fb0, st, 64); }
        if (!sk[3]) { A_MMA_HALF(0, fb1, st, 96); A_MMA_HALF(1, fb1, st, 96); }
    }

    // Epilogue.
    const int g = lane >> 2, tg = lane & 3;
    #pragma unroll
    for (int mi = 0; mi < 2; mi++)
        #pragma unroll
        for (int ni = 0; ni < 8; ni++) {
            const int r0 = m0 + wm + mi * 16 + g;
            const int c0 = n0 + wn + ni * 8 + tg * 2;
            *reinterpret_cast<float2*>(C + (size_t)r0 * NDIM + c0) =
                make_float2(acc[mi][ni][0], acc[mi][ni][1]);
            *reinterpret_cast<float2*>(C + (size_t)(r0 + 8) * NDIM + c0) =
                make_float2(acc[mi][ni][2], acc[mi][ni][3]);
        }
}

// ---------------------------------------------------------------------------
extern "C" void kernel_launch(void* const* d_in, const int* in_sizes, int n_in,
                              void* d_out, int out_size) {
    (void)in_sizes; (void)n_in; (void)out_size;
    const float* A = (const float*)d_in[0];
    const float* B = (const float*)d_in[1];
    float* C = (float*)d_out;

    static bool attr_done = false;
    if (!attr_done) {
        cudaFuncSetAttribute(trimm_kernel, cudaFuncAttributeMaxDynamicSharedMemorySize,
                             DSMEM_BYTES);
        attr_done = true;
    }

    conv_kernel<<<dim3(128, 128, 2), 256>>>(A, B);
    trimm_kernel<<<1024, 256, DSMEM_BYTES>>>(C);
}

// round 9
// speedup vs baseline: 1.0864x; 1.0602x over previous
#include <cuda_runtime.h>
#include <cuda_fp16.h>
#include <cstdint>
#include <cstddef>

#define NDIM   4096
#define BT     128
#define KT     64
#define STAGES 3
#define SROW   144            // smem bytes per tile row (128B data + 16B pad)
#define TILE_B (128 * SROW)
#define STAGE_B (2 * TILE_B)
#define DSMEM_BYTES (STAGES * STAGE_B)  // 110592 B -> 2 CTAs/SM

#define NSPLIT 136            // tiles with d >= 16 (split into 2 k-halves)
#define NJOBS  664            // 2*136 + 392

static __device__ __half g_Ah[(size_t)NDIM * NDIM];
static __device__ __half g_Bh[(size_t)NDIM * NDIM];   // [n][k]
static __device__ float  g_part[(size_t)NSPLIT * BT * BT];  // half1 partials

// ---------------------------------------------------------------------------
// Fused pre-pass over 32x32 tiles.
//  z=0: A -> fp16 (tiles with ct <= rt|3)
//  z=1: B -> Bh[n][k] transpose (k-tiles >= nt & ~3)
//  z=2: zero-fill strictly-upper 128-blocks of C
// ---------------------------------------------------------------------------
__global__ void conv_kernel(const float* __restrict__ A, const float* __restrict__ B,
                            float* __restrict__ C) {
    __shared__ float tile[32][33];
    const int tid = threadIdx.x;

    if (blockIdx.z == 0) {
        const int rt = blockIdx.y, ct = blockIdx.x;
        if (ct > (rt | 3)) return;
        const int r = rt * 32 + (tid >> 3);
        const int c = ct * 32 + (tid & 7) * 4;
        const float4 v = *reinterpret_cast<const float4*>(A + (size_t)r * NDIM + c);
        *reinterpret_cast<ushort4*>(g_Ah + (size_t)r * NDIM + c) =
            make_ushort4(__half_as_ushort(__float2half(v.x)),
                         __half_as_ushort(__float2half(v.y)),
                         __half_as_ushort(__float2half(v.z)),
                         __half_as_ushort(__float2half(v.w)));
        return;
    }
    if (blockIdx.z == 2) {
        const int rt = blockIdx.y, ct = blockIdx.x;
        if ((rt >> 2) >= (ct >> 2)) return;          // only strictly-upper 128-blocks
        const int r = rt * 32 + (tid >> 3);
        const int c = ct * 32 + (tid & 7) * 4;
        *reinterpret_cast<float4*>(C + (size_t)r * NDIM + c) =
            make_float4(0.f, 0.f, 0.f, 0.f);
        return;
    }

    const int nt = blockIdx.y, kt = blockIdx.x;
    if (kt < (nt & ~3)) return;
    const int bk = kt * 32, bn = nt * 32;
    const int x = tid & 31, y0 = tid >> 5;
    #pragma unroll
    for (int yy = y0; yy < 32; yy += 8)
        tile[yy][x] = B[(size_t)(bk + yy) * NDIM + bn + x];
    __syncthreads();
    #pragma unroll
    for (int yy = y0; yy < 32; yy += 8)
        g_Bh[(size_t)(bn + yy) * NDIM + bk + x] = __float2half(tile[x][yy]);
}

// ---------------------------------------------------------------------------
__device__ __forceinline__ uint32_t smem_u32(const void* p) {
    uint32_t a;
    asm("{ .reg .u64 t; cvta.to.shared.u64 t, %1; cvt.u32.u64 %0, t; }" : "=r"(a) : "l"(p));
    return a;
}
__device__ __forceinline__ void cpa16(uint32_t dst, const void* src) {
    asm volatile("cp.async.cg.shared.global [%0], [%1], 16;\n" ::"r"(dst), "l"(src));
}

#define LDSM4(r0, r1, r2, r3, addr)                                                    \
    asm volatile("ldmatrix.sync.aligned.m8n8.x4.shared.b16 {%0,%1,%2,%3}, [%4];"       \
                 : "=r"(r0), "=r"(r1), "=r"(r2), "=r"(r3) : "r"(addr))

#define MMA_F16(d, a, b0, b1)                                                          \
    asm volatile(                                                                      \
        "mma.sync.aligned.m16n8k16.row.col.f32.f16.f16.f32 "                           \
        "{%0,%1,%2,%3}, {%4,%5,%6,%7}, {%8,%9}, {%0,%1,%2,%3};\n"                      \
        : "+f"((d)[0]), "+f"((d)[1]), "+f"((d)[2]), "+f"((d)[3])                       \
        : "r"((a)[0]), "r"((a)[1]), "r"((a)[2]), "r"((a)[3]), "r"(b0), "r"(b1))

// ---------------------------------------------------------------------------
// Triangular GEMM with split-K jobs.
//  Jobs 0..271:   split tiles (d>=16), job=(pair p=j>>1, half h=j&1),
//                 chunks [h*(d+1), (h+1)*(d+1)); h0 -> C, h1 -> g_part[p].
//  Jobs 272..663: unsplit tiles (d<=15), chunks [0, 2(d+1)).
//  Ordering is work-descending (LPT).
// ---------------------------------------------------------------------------
__global__ __launch_bounds__(256, 2) void trimm_kernel(float* __restrict__ C) {
    extern __shared__ char dsm[];
    const int tid = threadIdx.x;
    const int lane = tid & 31, warp = tid >> 5;

    int bm, bn, c0, c1, sidx = 0;
    bool to_scratch = false;
    if (blockIdx.x < 2 * NSPLIT) {
        int p = blockIdx.x >> 1;
        const int h = blockIdx.x & 1;
        sidx = p;
        int d = 31;
        #pragma unroll 1
        while (p >= 32 - d) { p -= 32 - d; d--; }    // d: 31..16
        bn = p; bm = p + d;
        c0 = h * (d + 1); c1 = c0 + (d + 1);
        to_scratch = (h == 1);
    } else {
        int q = blockIdx.x - 2 * NSPLIT;
        int d = 15;
        #pragma unroll 1
        while (q >= 32 - d) { q -= 32 - d; d--; }    // d: 15..0
        bn = q; bm = q + d;
        c0 = 0; c1 = 2 * (d + 1);
    }

    const int m0 = bm * BT, n0 = bn * BT;
    const uint32_t sb = smem_u32(dsm);

    // cp.async mapping: 4 cps per tile per thread.
    const int cr0 = tid >> 3, cc = tid & 7;
    const __half* gAh = g_Ah + (size_t)(m0 + cr0) * NDIM + cc * 8;
    const __half* gBh = g_Bh + (size_t)(n0 + cr0) * NDIM + cc * 8;
    const uint32_t cdst = sb + cr0 * SROW + cc * 16;

    // Warp tile 32m x 64n.
    const int wm = (warp >> 1) * 32, wn = (warp & 1) * 64;
    const int mlim = m0 + wm + 31;                // A slice zero if k0 > mlim
    const int nlim = n0 + wn;                     // B slice zero if k0+16 <= nlim
    uint32_t a_off[2], b_off[4];
    #pragma unroll
    for (int mi = 0; mi < 2; mi++)
        a_off[mi] = (uint32_t)((wm + mi * 16 + (lane & 15)) * SROW + (lane >> 4) * 16);
    #pragma unroll
    for (int p = 0; p < 4; p++) {
        const int quad = lane >> 3;
        b_off[p] = (uint32_t)(TILE_B + (wn + p * 16 + (quad >> 1) * 8 + (lane & 7)) * SROW +
                              (quad & 1) * 16);
    }

    float acc[2][8][4];
    #pragma unroll
    for (int mi = 0; mi < 2; mi++)
        #pragma unroll
        for (int ni = 0; ni < 8; ni++)
            #pragma unroll
            for (int r = 0; r < 4; r++) acc[mi][ni][r] = 0.f;

    // Prologue: commit chunks c0, c0+1 (every job has >= 2 chunks).
    #pragma unroll
    for (int s = 0; s < STAGES - 1; s++) {
        const int k0 = n0 + (c0 + s) * KT;
        const uint32_t d = cdst + s * STAGE_B;
        #pragma unroll
        for (int i = 0; i < 4; i++) {
            cpa16(d + i * 32 * SROW, gAh + (size_t)i * 32 * NDIM + k0);
            cpa16(d + TILE_B + i * 32 * SROW, gBh + (size_t)i * 32 * NDIM + k0);
        }
        asm volatile("cp.async.commit_group;\n");
    }

    #pragma unroll 1
    for (int it = c0; it < c1; it++) {
        const int k0 = n0 + it * KT;
        asm volatile("cp.async.wait_group 1;\n");   // chunk it resident
        __syncthreads();                            // visible; warps past it-1

        const int ch = it + 2;
        if (ch < c1) {
            const int kp = n0 + ch * KT;
            const uint32_t d = cdst + ((ch - c0) % STAGES) * STAGE_B;
            #pragma unroll
            for (int i = 0; i < 4; i++) {
                cpa16(d + i * 32 * SROW, gAh + (size_t)i * 32 * NDIM + kp);
                cpa16(d + TILE_B + i * 32 * SROW, gBh + (size_t)i * 32 * NDIM + kp);
            }
        }
        asm volatile("cp.async.commit_group;\n");

        const uint32_t st = sb + ((it - c0) % STAGES) * STAGE_B;

        bool sk[4];
        #pragma unroll
        for (int kk = 0; kk < 4; kk++)
            sk[kk] = (k0 + 16 * kk > mlim) || (k0 + 16 * kk + 16 <= nlim);

        #pragma unroll
        for (int kk = 0; kk < 4; kk++) {
            if (sk[kk]) continue;
            const uint32_t kb = kk * 32;
            uint32_t ah[2][4], bb[4][4];
            LDSM4(ah[0][0], ah[0][1], ah[0][2], ah[0][3], st + a_off[0] + kb);
            LDSM4(ah[1][0], ah[1][1], ah[1][2], ah[1][3], st + a_off[1] + kb);
            #pragma unroll
            for (int p = 0; p < 4; p++)
                LDSM4(bb[p][0], bb[p][1], bb[p][2], bb[p][3], st + b_off[p] + kb);
            #pragma unroll
            for (int mi = 0; mi < 2; mi++)
                #pragma unroll
                for (int p = 0; p < 4; p++) {
                    MMA_F16(acc[mi][2 * p],     ah[mi], bb[p][0], bb[p][1]);
                    MMA_F16(acc[mi][2 * p + 1], ah[mi], bb[p][2], bb[p][3]);
                }
        }
    }

    // Epilogue: full tile to C (h0 / unsplit) or to scratch (h1).
    const int g = lane >> 2, tg = lane & 3;
    if (to_scratch) {
        float* P = g_part + (size_t)sidx * BT * BT;
        #pragma unroll
        for (int mi = 0; mi < 2; mi++)
            #pragma unroll
            for (int ni = 0; ni < 8; ni++) {
                const int lr = wm + mi * 16 + g;
                const int lc = wn + ni * 8 + tg * 2;
                *reinterpret_cast<float2*>(P + lr * BT + lc) =
                    make_float2(acc[mi][ni][0], acc[mi][ni][1]);
                *reinterpret_cast<float2*>(P + (lr + 8) * BT + lc) =
                    make_float2(acc[mi][ni][2], acc[mi][ni][3]);
            }
    } else {
        #pragma unroll
        for (int mi = 0; mi < 2; mi++)
            #pragma unroll
            for (int ni = 0; ni < 8; ni++) {
                const int r0 = m0 + wm + mi * 16 + g;
                const int c0g = n0 + wn + ni * 8 + tg * 2;
                *reinterpret_cast<float2*>(C + (size_t)r0 * NDIM + c0g) =
                    make_float2(acc[mi][ni][0], acc[mi][ni][1]);
                *reinterpret_cast<float2*>(C + (size_t)(r0 + 8) * NDIM + c0g) =
                    make_float2(acc[mi][ni][2], acc[mi][ni][3]);
            }
    }
}

// ---------------------------------------------------------------------------
// Combine: C[tile p] += g_part[p] for the 136 split tiles.
// ---------------------------------------------------------------------------
__global__ void combine_kernel(float* __restrict__ C) {
    int p = blockIdx.x, d = 31;
    #pragma unroll 1
    while (p >= 32 - d) { p -= 32 - d; d--; }
    const int m0 = (p + d) * BT, n0 = p * BT;
    const float4* P = reinterpret_cast<const float4*>(g_part + (size_t)blockIdx.x * BT * BT);
    #pragma unroll 1
    for (int i = threadIdx.x; i < BT * BT / 4; i += 256) {
        const int r = i >> 5, c4 = i & 31;
        float4 v = P[i];
        float4* dst = reinterpret_cast<float4*>(C + (size_t)(m0 + r) * NDIM + n0) + c4;
        float4 o = *dst;
        o.x += v.x; o.y += v.y; o.z += v.z; o.w += v.w;
        *dst = o;
    }
}

// ---------------------------------------------------------------------------
extern "C" void kernel_launch(void* const* d_in, const int* in_sizes, int n_in,
                              void* d_out, int out_size) {
    (void)in_sizes; (void)n_in; (void)out_size;
    const float* A = (const float*)d_in[0];
    const float* B = (const float*)d_in[1];
    float* C = (float*)d_out;

    static bool attr_done = false;
    if (!attr_done) {
        cudaFuncSetAttribute(trimm_kernel, cudaFuncAttributeMaxDynamicSharedMemorySize,
                             DSMEM_BYTES);
        attr_done = true;
    }

    conv_kernel<<<dim3(128, 128, 3), 256>>>(A, B, C);
    trimm_kernel<<<NJOBS, 256, DSMEM_BYTES>>>(C);
    combine_kernel<<<NSPLIT, 256>>>(C);
}

// round 10
// speedup vs baseline: 1.3548x; 1.2471x over previous
#include <cuda_runtime.h>
#include <cuda_fp16.h>
#include <cstdint>
#include <cstddef>

#define NDIM   4096
#define BT     128
#define KT     64
#define STAGES 3
#define SROW   144            // smem bytes per tile row (128B data + 16B pad)
#define TILE_B (128 * SROW)
#define STAGE_B (2 * TILE_B)
#define DSMEM_BYTES (STAGES * STAGE_B)  // 110592 B -> 2 CTAs/SM

#define NSPLIT 136            // tiles with d >= 16 (split into 2 k-halves)
#define NJOBS  664            // 2*136 + 392

static __device__ __half g_Ah[(size_t)NDIM * NDIM];
static __device__ __half g_Bh[(size_t)NDIM * NDIM];   // [n][k]

// ---------------------------------------------------------------------------
// Fused pre-pass over 64x64 tiles, grid (64,64,3), 256 thr.
//  z=0: A -> fp16 (tiles with ct <= rt|1)
//  z=1: B[k][n] -> Bh[n][k] transpose+convert (k-tiles with kt >= nt&~1)
//  z=2: zero C for strictly-upper 128-blocks AND the 136 split lower tiles
// Each thread moves 4 float4s (16 independent loads in flight per phase).
// ---------------------------------------------------------------------------
__global__ void conv_kernel(const float* __restrict__ A, const float* __restrict__ B,
                            float* __restrict__ C) {
    __shared__ float t64[64][65];
    const int tid = threadIdx.x;

    if (blockIdx.z == 0) {
        const int rt = blockIdx.y, ct = blockIdx.x;
        if (ct > (rt | 1)) return;
        #pragma unroll
        for (int j = 0; j < 4; j++) {
            const int idx = tid + 256 * j;             // 0..1023 over 64 rows x 16 f4
            const int r = rt * 64 + (idx >> 4);
            const int c = ct * 64 + (idx & 15) * 4;
            const float4 v = *reinterpret_cast<const float4*>(A + (size_t)r * NDIM + c);
            *reinterpret_cast<ushort4*>(g_Ah + (size_t)r * NDIM + c) =
                make_ushort4(__half_as_ushort(__float2half(v.x)),
                             __half_as_ushort(__float2half(v.y)),
                             __half_as_ushort(__float2half(v.z)),
                             __half_as_ushort(__float2half(v.w)));
        }
        return;
    }

    if (blockIdx.z == 2) {
        const int rt = blockIdx.y, ct = blockIdx.x;
        const int rb = rt >> 1, cb = ct >> 1;          // 128-block coords
        const bool upper = rb < cb;
        const bool split = (rb - cb) >= 16;
        if (!upper && !split) return;
        #pragma unroll
        for (int j = 0; j < 4; j++) {
            const int idx = tid + 256 * j;
            const int r = rt * 64 + (idx >> 4);
            const int c = ct * 64 + (idx & 15) * 4;
            *reinterpret_cast<float4*>(C + (size_t)r * NDIM + c) =
                make_float4(0.f, 0.f, 0.f, 0.f);
        }
        return;
    }

    // z=1: transpose B 64x64 tile (kt, nt).
    const int kt = blockIdx.x, nt = blockIdx.y;
    if (kt < (nt & ~1)) return;
    const int bk = kt * 64, bn = nt * 64;
    #pragma unroll
    for (int j = 0; j < 4; j++) {
        const int idx = tid + 256 * j;
        const int kr = idx >> 4, c4 = (idx & 15) * 4;
        const float4 v = *reinterpret_cast<const float4*>(B + (size_t)(bk + kr) * NDIM + bn + c4);
        t64[kr][c4 + 0] = v.x; t64[kr][c4 + 1] = v.y;
        t64[kr][c4 + 2] = v.z; t64[kr][c4 + 3] = v.w;
    }
    __syncthreads();
    #pragma unroll
    for (int j = 0; j < 2; j++) {
        const int idx = tid + 256 * j;                 // 0..511 over 64 n-rows x 8 chunks
        const int nr = idx >> 3, kc = idx & 7;         // 8 halfs (16B) per chunk
        ushort4 o0, o1;
        o0.x = __half_as_ushort(__float2half(t64[kc * 8 + 0][nr]));
        o0.y = __half_as_ushort(__float2half(t64[kc * 8 + 1][nr]));
        o0.z = __half_as_ushort(__float2half(t64[kc * 8 + 2][nr]));
        o0.w = __half_as_ushort(__float2half(t64[kc * 8 + 3][nr]));
        o1.x = __half_as_ushort(__float2half(t64[kc * 8 + 4][nr]));
        o1.y = __half_as_ushort(__float2half(t64[kc * 8 + 5][nr]));
        o1.z = __half_as_ushort(__float2half(t64[kc * 8 + 6][nr]));
        o1.w = __half_as_ushort(__float2half(t64[kc * 8 + 7][nr]));
        ushort4* dst = reinterpret_cast<ushort4*>(g_Bh + (size_t)(bn + nr) * NDIM + bk + kc * 8);
        dst[0] = o0; dst[1] = o1;
    }
}

// ---------------------------------------------------------------------------
__device__ __forceinline__ uint32_t smem_u32(const void* p) {
    uint32_t a;
    asm("{ .reg .u64 t; cvta.to.shared.u64 t, %1; cvt.u32.u64 %0, t; }" : "=r"(a) : "l"(p));
    return a;
}
__device__ __forceinline__ void cpa16(uint32_t dst, const void* src) {
    asm volatile("cp.async.cg.shared.global [%0], [%1], 16;\n" ::"r"(dst), "l"(src));
}

#define LDSM4(r0, r1, r2, r3, addr)                                                    \
    asm volatile("ldmatrix.sync.aligned.m8n8.x4.shared.b16 {%0,%1,%2,%3}, [%4];"       \
                 : "=r"(r0), "=r"(r1), "=r"(r2), "=r"(r3) : "r"(addr))

#define MMA_F16(d, a, b0, b1)                                                          \
    asm volatile(                                                                      \
        "mma.sync.aligned.m16n8k16.row.col.f32.f16.f16.f32 "                           \
        "{%0,%1,%2,%3}, {%4,%5,%6,%7}, {%8,%9}, {%0,%1,%2,%3};\n"                      \
        : "+f"((d)[0]), "+f"((d)[1]), "+f"((d)[2]), "+f"((d)[3])                       \
        : "r"((a)[0]), "r"((a)[1]), "r"((a)[2]), "r"((a)[3]), "r"(b0), "r"(b1))

// ---------------------------------------------------------------------------
// Triangular GEMM with split-K jobs.
//  Jobs 0..271:   split tiles (d>=16), job=(pair p=j>>1, half h=j&1),
//                 chunks [h*(d+1), (h+1)*(d+1)); both halves RED.ADD into C
//                 (their C tiles are pre-zeroed by conv z=2).
//  Jobs 272..663: unsplit tiles (d<=15), full k range, plain stores.
// ---------------------------------------------------------------------------
__global__ __launch_bounds__(256, 2) void trimm_kernel(float* __restrict__ C) {
    extern __shared__ char dsm[];
    const int tid = threadIdx.x;
    const int lane = tid & 31, warp = tid >> 5;

    int bm, bn, c0, c1;
    bool use_red = false;
    if (blockIdx.x < 2 * NSPLIT) {
        int p = blockIdx.x >> 1;
        const int h = blockIdx.x & 1;
        int d = 31;
        #pragma unroll 1
        while (p >= 32 - d) { p -= 32 - d; d--; }    // d: 31..16
        bn = p; bm = p + d;
        c0 = h * (d + 1); c1 = c0 + (d + 1);
        use_red = true;
    } else {
        int q = blockIdx.x - 2 * NSPLIT;
        int d = 15;
        #pragma unroll 1
        while (q >= 32 - d) { q -= 32 - d; d--; }    // d: 15..0
        bn = q; bm = q + d;
        c0 = 0; c1 = 2 * (d + 1);
    }

    const int m0 = bm * BT, n0 = bn * BT;
    const uint32_t sb = smem_u32(dsm);

    // cp.async mapping: 4 cps per tile per thread.
    const int cr0 = tid >> 3, cc = tid & 7;
    const __half* gAh = g_Ah + (size_t)(m0 + cr0) * NDIM + cc * 8;
    const __half* gBh = g_Bh + (size_t)(n0 + cr0) * NDIM + cc * 8;
    const uint32_t cdst = sb + cr0 * SROW + cc * 16;

    // Warp tile 32m x 64n.
    const int wm = (warp >> 1) * 32, wn = (warp & 1) * 64;
    const int mlim = m0 + wm + 31;                // A slice zero if k0 > mlim
    const int nlim = n0 + wn;                     // B slice zero if k0+16 <= nlim
    uint32_t a_off[2], b_off[4];
    #pragma unroll
    for (int mi = 0; mi < 2; mi++)
        a_off[mi] = (uint32_t)((wm + mi * 16 + (lane & 15)) * SROW + (lane >> 4) * 16);
    #pragma unroll
    for (int p = 0; p < 4; p++) {
        const int quad = lane >> 3;
        b_off[p] = (uint32_t)(TILE_B + (wn + p * 16 + (quad >> 1) * 8 + (lane & 7)) * SROW +
                              (quad & 1) * 16);
    }

    float acc[2][8][4];
    #pragma unroll
    for (int mi = 0; mi < 2; mi++)
        #pragma unroll
        for (int ni = 0; ni < 8; ni++)
            #pragma unroll
            for (int r = 0; r < 4; r++) acc[mi][ni][r] = 0.f;

    // Prologue: commit chunks c0, c0+1 (every job has >= 2 chunks).
    #pragma unroll
    for (int s = 0; s < STAGES - 1; s++) {
        const int k0 = n0 + (c0 + s) * KT;
        const uint32_t d = cdst + s * STAGE_B;
        #pragma unroll
        for (int i = 0; i < 4; i++) {
            cpa16(d + i * 32 * SROW, gAh + (size_t)i * 32 * NDIM + k0);
            cpa16(d + TILE_B + i * 32 * SROW, gBh + (size_t)i * 32 * NDIM + k0);
        }
        asm volatile("cp.async.commit_group;\n");
    }

    #pragma unroll 1
    for (int it = c0; it < c1; it++) {
        const int k0 = n0 + it * KT;
        asm volatile("cp.async.wait_group 1;\n");   // chunk it resident
        __syncthreads();                            // visible; warps past it-1

        const int ch = it + 2;
        if (ch < c1) {
            const int kp = n0 + ch * KT;
            const uint32_t d = cdst + ((ch - c0) % STAGES) * STAGE_B;
            #pragma unroll
            for (int i = 0; i < 4; i++) {
                cpa16(d + i * 32 * SROW, gAh + (size_t)i * 32 * NDIM + kp);
                cpa16(d + TILE_B + i * 32 * SROW, gBh + (size_t)i * 32 * NDIM + kp);
            }
        }
        asm volatile("cp.async.commit_group;\n");

        const uint32_t st = sb + ((it - c0) % STAGES) * STAGE_B;

        bool sk[4];
        #pragma unroll
        for (int kk = 0; kk < 4; kk++)
            sk[kk] = (k0 + 16 * kk > mlim) || (k0 + 16 * kk + 16 <= nlim);

        #pragma unroll
        for (int kk = 0; kk < 4; kk++) {
            if (sk[kk]) continue;
            const uint32_t kb = kk * 32;
            uint32_t ah[2][4], bb[4][4];
            LDSM4(ah[0][0], ah[0][1], ah[0][2], ah[0][3], st + a_off[0] + kb);
            LDSM4(ah[1][0], ah[1][1], ah[1][2], ah[1][3], st + a_off[1] + kb);
            #pragma unroll
            for (int p = 0; p < 4; p++)
                LDSM4(bb[p][0], bb[p][1], bb[p][2], bb[p][3], st + b_off[p] + kb);
            #pragma unroll
            for (int mi = 0; mi < 2; mi++)
                #pragma unroll
                for (int p = 0; p < 4; p++) {
                    MMA_F16(acc[mi][2 * p],     ah[mi], bb[p][0], bb[p][1]);
                    MMA_F16(acc[mi][2 * p + 1], ah[mi], bb[p][2], bb[p][3]);
                }
        }
    }

    // Epilogue.
    const int g = lane >> 2, tg = lane & 3;
    if (use_red) {
        #pragma unroll
        for (int mi = 0; mi < 2; mi++)
            #pragma unroll
            for (int ni = 0; ni < 8; ni++) {
                const int r0 = m0 + wm + mi * 16 + g;
                const int c0g = n0 + wn + ni * 8 + tg * 2;
                float* p0 = C + (size_t)r0 * NDIM + c0g;
                float* p1 = C + (size_t)(r0 + 8) * NDIM + c0g;
                atomicAdd(p0,     acc[mi][ni][0]);
                atomicAdd(p0 + 1, acc[mi][ni][1]);
                atomicAdd(p1,     acc[mi][ni][2]);
                atomicAdd(p1 + 1, acc[mi][ni][3]);
            }
    } else {
        #pragma unroll
        for (int mi = 0; mi < 2; mi++)
            #pragma unroll
            for (int ni = 0; ni < 8; ni++) {
                const int r0 = m0 + wm + mi * 16 + g;
                const int c0g = n0 + wn + ni * 8 + tg * 2;
                *reinterpret_cast<float2*>(C + (size_t)r0 * NDIM + c0g) =
                    make_float2(acc[mi][ni][0], acc[mi][ni][1]);
                *reinterpret_cast<float2*>(C + (size_t)(r0 + 8) * NDIM + c0g) =
                    make_float2(acc[mi][ni][2], acc[mi][ni][3]);
            }
    }
}

// ---------------------------------------------------------------------------
extern "C" void kernel_launch(void* const* d_in, const int* in_sizes, int n_in,
                              void* d_out, int out_size) {
    (void)in_sizes; (void)n_in; (void)out_size;
    const float* A = (const float*)d_in[0];
    const float* B = (const float*)d_in[1];
    float* C = (float*)d_out;

    static bool attr_done = false;
    if (!attr_done) {
        cudaFuncSetAttribute(trimm_kernel, cudaFuncAttributeMaxDynamicSharedMemorySize,
                             DSMEM_BYTES);
        attr_done = true;
    }

    conv_kernel<<<dim3(64, 64, 3), 256>>>(A, B, C);
    trimm_kernel<<<NJOBS, 256, DSMEM_BYTES>>>(C);
}

// round 12
// speedup vs baseline: 1.3560x; 1.0009x over previous
#include <cuda_runtime.h>
#include <cuda_fp16.h>
#include <cstdint>
#include <cstddef>

#define NDIM   4096
#define BT     128
#define KT     64
#define STAGES 3
#define SROW   144            // smem bytes per tile row (128B data + 16B pad)
#define TILE_B (128 * SROW)
#define STAGE_B (2 * TILE_B)
#define DSMEM_BYTES (STAGES * STAGE_B)  // 110592 B -> 2 CTAs/SM

#define NSPLIT 136            // tiles with d >= 16 (split into 2 k-halves)
#define NJOBS  664            // 2*136 + 392 compute jobs
#define NZERO  496            // strictly-upper 128-blocks (zero-fill tail CTAs)

static __device__ __half g_Ah[(size_t)NDIM * NDIM];
static __device__ __half g_Bh[(size_t)NDIM * NDIM];   // [n][k]

// ---------------------------------------------------------------------------
// Fused pre-pass over 64x64 tiles, grid (64,64,3), 256 thr.
//  z=0: A -> fp16 (tiles with ct <= rt|1)
//  z=1: B[k][n] -> Bh[n][k] transpose+convert (k-tiles with kt >= nt&~1)
//  z=2: zero C ONLY for the 136 split lower tiles (atomicAdd targets).
//       Upper-triangle zeroing moved to trimm tail CTAs (DRAM idle there).
// ---------------------------------------------------------------------------
__global__ void conv_kernel(const float* __restrict__ A, const float* __restrict__ B,
                            float* __restrict__ C) {
    __shared__ float t64[64][65];
    const int tid = threadIdx.x;

    if (blockIdx.z == 0) {
        const int rt = blockIdx.y, ct = blockIdx.x;
        if (ct > (rt | 1)) return;
        #pragma unroll
        for (int j = 0; j < 4; j++) {
            const int idx = tid + 256 * j;             // 64 rows x 16 float4
            const int r = rt * 64 + (idx >> 4);
            const int c = ct * 64 + (idx & 15) * 4;
            const float4 v = *reinterpret_cast<const float4*>(A + (size_t)r * NDIM + c);
            *reinterpret_cast<ushort4*>(g_Ah + (size_t)r * NDIM + c) =
                make_ushort4(__half_as_ushort(__float2half(v.x)),
                             __half_as_ushort(__float2half(v.y)),
                             __half_as_ushort(__float2half(v.z)),
                             __half_as_ushort(__float2half(v.w)));
        }
        return;
    }

    if (blockIdx.z == 2) {
        const int rt = blockIdx.y, ct = blockIdx.x;
        const int rb = rt >> 1, cb = ct >> 1;          // 128-block coords
        if (rb - cb < 16) return;                      // only split tiles
        #pragma unroll
        for (int j = 0; j < 4; j++) {
            const int idx = tid + 256 * j;
            const int r = rt * 64 + (idx >> 4);
            const int c = ct * 64 + (idx & 15) * 4;
            *reinterpret_cast<float4*>(C + (size_t)r * NDIM + c) =
                make_float4(0.f, 0.f, 0.f, 0.f);
        }
        return;
    }

    // z=1: transpose B 64x64 tile (kt, nt).
    const int kt = blockIdx.x, nt = blockIdx.y;
    if (kt < (nt & ~1)) return;
    const int bk = kt * 64, bn = nt * 64;
    #pragma unroll
    for (int j = 0; j < 4; j++) {
        const int idx = tid + 256 * j;
        const int kr = idx >> 4, c4 = (idx & 15) * 4;
        const float4 v = *reinterpret_cast<const float4*>(B + (size_t)(bk + kr) * NDIM + bn + c4);
        t64[kr][c4 + 0] = v.x; t64[kr][c4 + 1] = v.y;
        t64[kr][c4 + 2] = v.z; t64[kr][c4 + 3] = v.w;
    }
    __syncthreads();
    #pragma unroll
    for (int j = 0; j < 2; j++) {
        const int idx = tid + 256 * j;                 // 64 n-rows x 8 16B-chunks
        const int nr = idx >> 3, kc = idx & 7;
        ushort4 o0, o1;
        o0.x = __half_as_ushort(__float2half(t64[kc * 8 + 0][nr]));
        o0.y = __half_as_ushort(__float2half(t64[kc * 8 + 1][nr]));
        o0.z = __half_as_ushort(__float2half(t64[kc * 8 + 2][nr]));
        o0.w = __half_as_ushort(__float2half(t64[kc * 8 + 3][nr]));
        o1.x = __half_as_ushort(__float2half(t64[kc * 8 + 4][nr]));
        o1.y = __half_as_ushort(__float2half(t64[kc * 8 + 5][nr]));
        o1.z = __half_as_ushort(__float2half(t64[kc * 8 + 6][nr]));
        o1.w = __half_as_ushort(__float2half(t64[kc * 8 + 7][nr]));
        ushort4* dst = reinterpret_cast<ushort4*>(g_Bh + (size_t)(bn + nr) * NDIM + bk + kc * 8);
        dst[0] = o0; dst[1] = o1;
    }
}

// ---------------------------------------------------------------------------
__device__ __forceinline__ uint32_t smem_u32(const void* p) {
    uint32_t a;
    asm("{ .reg .u64 t; cvta.to.shared.u64 t, %1; cvt.u32.u64 %0, t; }" : "=r"(a) : "l"(p));
    return a;
}
__device__ __forceinline__ void cpa16(uint32_t dst, const void* src) {
    asm volatile("cp.async.cg.shared.global [%0], [%1], 16;\n" ::"r"(dst), "l"(src));
}

#define LDSM4(r0, r1, r2, r3, addr)                                                    \
    asm volatile("ldmatrix.sync.aligned.m8n8.x4.shared.b16 {%0,%1,%2,%3}, [%4];"       \
                 : "=r"(r0), "=r"(r1), "=r"(r2), "=r"(r3) : "r"(addr))

#define MMA_F16(d, a, b0, b1)                                                          \
    asm volatile(                                                                      \
        "mma.sync.aligned.m16n8k16.row.col.f32.f16.f16.f32 "                           \
        "{%0,%1,%2,%3}, {%4,%5,%6,%7}, {%8,%9}, {%0,%1,%2,%3};\n"                      \
        : "+f"((d)[0]), "+f"((d)[1]), "+f"((d)[2]), "+f"((d)[3])                       \
        : "r"((a)[0]), "r"((a)[1]), "r"((a)[2]), "r"((a)[3]), "r"(b0), "r"(b1))

// ---------------------------------------------------------------------------
// Triangular GEMM with split-K jobs + zero-fill tail CTAs.
//  Jobs 0..271:    split tiles (d>=16): pair p=j>>1, half h=j&1,
//                  chunks [h*(d+1), (h+1)*(d+1)); both halves RED.ADD into
//                  pre-zeroed C.
//  Jobs 272..663:  unsplit tiles (d<=15), full k range, plain stores.
//  Jobs 664..1159: strictly-upper 128-blocks: zero-fill (run in the tail).
// ---------------------------------------------------------------------------
__global__ __launch_bounds__(256, 2) void trimm_kernel(float* __restrict__ C) {
    extern __shared__ char dsm[];
    const int tid = threadIdx.x;
    const int lane = tid & 31, warp = tid >> 5;

    if (blockIdx.x >= NJOBS) {
        // Zero-fill one strictly-upper 128x128 block.
        int u = blockIdx.x - NJOBS, r = 0;
        #pragma unroll 1
        while (u >= 31 - r) { u -= 31 - r; r++; }
        const int m0 = r * BT, n0 = (r + 1 + u) * BT;
        const float4 z = make_float4(0.f, 0.f, 0.f, 0.f);
        #pragma unroll 1
        for (int i = tid; i < 128 * 32; i += 256)
            reinterpret_cast<float4*>(C + (size_t)(m0 + (i >> 5)) * NDIM + n0)[i & 31] = z;
        return;
    }

    int bm, bn, c0, c1;
    bool use_red = false;
    if (blockIdx.x < 2 * NSPLIT) {
        int p = blockIdx.x >> 1;
        const int h = blockIdx.x & 1;
        int d = 31;
        #pragma unroll 1
        while (p >= 32 - d) { p -= 32 - d; d--; }    // d: 31..16
        bn = p; bm = p + d;
        c0 = h * (d + 1); c1 = c0 + (d + 1);
        use_red = true;
    } else {
        int q = blockIdx.x - 2 * NSPLIT;
        int d = 15;
        #pragma unroll 1
        while (q >= 32 - d) { q -= 32 - d; d--; }    // d: 15..0
        bn = q; bm = q + d;
        c0 = 0; c1 = 2 * (d + 1);
    }

    const int m0 = bm * BT, n0 = bn * BT;
    const uint32_t sb = smem_u32(dsm);

    // cp.async mapping: 4 cps per tile per thread.
    const int cr0 = tid >> 3, cc = tid & 7;
    const __half* gAh = g_Ah + (size_t)(m0 + cr0) * NDIM + cc * 8;
    const __half* gBh = g_Bh + (size_t)(n0 + cr0) * NDIM + cc * 8;
    const uint32_t cdst = sb + cr0 * SROW + cc * 16;

    // Warp tile 32m x 64n.
    const int wm = (warp >> 1) * 32, wn = (warp & 1) * 64;
    const int mlim = m0 + wm + 31;                // A slice zero if k0 > mlim
    const int nlim = n0 + wn;                     // B slice zero if k0+16 <= nlim
    uint32_t a_off[2], b_off[4];
    #pragma unroll
    for (int mi = 0; mi < 2; mi++)
        a_off[mi] = (uint32_t)((wm + mi * 16 + (lane & 15)) * SROW + (lane >> 4) * 16);
    #pragma unroll
    for (int p = 0; p < 4; p++) {
        const int quad = lane >> 3;
        b_off[p] = (uint32_t)(TILE_B + (wn + p * 16 + (quad >> 1) * 8 + (lane & 7)) * SROW +
                              (quad & 1) * 16);
    }

    float acc[2][8][4];
    #pragma unroll
    for (int mi = 0; mi < 2; mi++)
        #pragma unroll
        for (int ni = 0; ni < 8; ni++)
            #pragma unroll
            for (int r = 0; r < 4; r++) acc[mi][ni][r] = 0.f;

    // Prologue: commit chunks c0, c0+1 (every job has >= 2 chunks).
    #pragma unroll
    for (int s = 0; s < STAGES - 1; s++) {
        const int k0 = n0 + (c0 + s) * KT;
        const uint32_t d = cdst + s * STAGE_B;
        #pragma unroll
        for (int i = 0; i < 4; i++) {
            cpa16(d + i * 32 * SROW, gAh + (size_t)i * 32 * NDIM + k0);
            cpa16(d + TILE_B + i * 32 * SROW, gBh + (size_t)i * 32 * NDIM + k0);
        }
        asm volatile("cp.async.commit_group;\n");
    }

    #pragma unroll 1
    for (int it = c0; it < c1; it++) {
        const int k0 = n0 + it * KT;
        asm volatile("cp.async.wait_group 1;\n");   // chunk it resident
        __syncthreads();                            // visible; warps past it-1

        const int ch = it + 2;
        if (ch < c1) {
            const int kp = n0 + ch * KT;
            const uint32_t d = cdst + ((ch - c0) % STAGES) * STAGE_B;
            #pragma unroll
            for (int i = 0; i < 4; i++) {
                cpa16(d + i * 32 * SROW, gAh + (size_t)i * 32 * NDIM + kp);
                cpa16(d + TILE_B + i * 32 * SROW, gBh + (size_t)i * 32 * NDIM + kp);
            }
        }
        asm volatile("cp.async.commit_group;\n");

        const uint32_t st = sb + ((it - c0) % STAGES) * STAGE_B;

        bool sk[4];
        #pragma unroll
        for (int kk = 0; kk < 4; kk++)
            sk[kk] = (k0 + 16 * kk > mlim) || (k0 + 16 * kk + 16 <= nlim);

        #pragma unroll
        for (int kk = 0; kk < 4; kk++) {
            if (sk[kk]) continue;
            const uint32_t kb = kk * 32;
            uint32_t ah[2][4], bb[4][4];
            LDSM4(ah[0][0], ah[0][1], ah[0][2], ah[0][3], st + a_off[0] + kb);
            LDSM4(ah[1][0], ah[1][1], ah[1][2], ah[1][3], st + a_off[1] + kb);
            #pragma unroll
            for (int p = 0; p < 4; p++)
                LDSM4(bb[p][0], bb[p][1], bb[p][2], bb[p][3], st + b_off[p] + kb);
            #pragma unroll
            for (int mi = 0; mi < 2; mi++)
                #pragma unroll
                for (int p = 0; p < 4; p++) {
                    MMA_F16(acc[mi][2 * p],     ah[mi], bb[p][0], bb[p][1]);
                    MMA_F16(acc[mi][2 * p + 1], ah[mi], bb[p][2], bb[p][3]);
                }
        }
    }

    // Epilogue.
    const int g = lane >> 2, tg = lane & 3;
    if (use_red) {
        #pragma unroll
        for (int mi = 0; mi < 2; mi++)
            #pragma unroll
            for (int ni = 0; ni < 8; ni++) {
                const int r0 = m0 + wm + mi * 16 + g;
                const int c0g = n0 + wn + ni * 8 + tg * 2;
                float* p0 = C + (size_t)r0 * NDIM + c0g;
                float* p1 = C + (size_t)(r0 + 8) * NDIM + c0g;
                atomicAdd(p0,     acc[mi][ni][0]);
                atomicAdd(p0 + 1, acc[mi][ni][1]);
                atomicAdd(p1,     acc[mi][ni][2]);
                atomicAdd(p1 + 1, acc[mi][ni][3]);
            }
    } else {
        #pragma unroll
        for (int mi = 0; mi < 2; mi++)
            #pragma unroll
            for (int ni = 0; ni < 8; ni++) {
                const int r0 = m0 + wm + mi * 16 + g;
                const int c0g = n0 + wn + ni * 8 + tg * 2;
                *reinterpret_cast<float2*>(C + (size_t)r0 * NDIM + c0g) =
                    make_float2(acc[mi][ni][0], acc[mi][ni][1]);
                *reinterpret_cast<float2*>(C + (size_t)(r0 + 8) * NDIM + c0g) =
                    make_float2(acc[mi][ni][2], acc[mi][ni][3]);
            }
    }
}

// ---------------------------------------------------------------------------
extern "C" void kernel_launch(void* const* d_in, const int* in_sizes, int n_in,
                              void* d_out, int out_size) {
    (void)in_sizes; (void)n_in; (void)out_size;
    const float* A = (const float*)d_in[0];
    const float* B = (const float*)d_in[1];
    float* C = (float*)d_out;

    static bool attr_done = false;
    if (!attr_done) {
        cudaFuncSetAttribute(trimm_kernel, cudaFuncAttributeMaxDynamicSharedMemorySize,
                             DSMEM_BYTES);
        attr_done = true;
    }

    conv_kernel<<<dim3(64, 64, 3), 256>>>(A, B, C);
    trimm_kernel<<<NJOBS + NZERO, 256, DSMEM_BYTES>>>(C);
}